// round 3
// baseline (speedup 1.0000x reference)
#include <cuda_runtime.h>

#define BATCHB 128
#define NPTS   4000
#define NAP1   401
#define BLOCK  512
#define CPT    8     // points per thread; 500 active threads cover 4000 points

// Evaluate f(u), |f'(u)|, A(u) for one point.
// f(u)  = 0.5*u*(3-u^2) + 25*u^2*(0.75 - 2u + 1.5u^2 - 0.25u^4)
// f'(u) = 1.5 + 37.5u - 151.5u^2 + 150u^3 - 37.5u^5
// A(u)  = two-ramp closed form of cumtrapz(0.5*a_real) interpolation:
//         0.25*(clamp(u,lo,mid)-lo) + 0.5*(clamp(u,mid,hi)-mid)
__device__ __forceinline__ void eval3(float v, float lo, float mid, float hi,
                                      float& fo, float& dd, float& Ao)
{
    float v2 = v * v;
    float p  = fmaf(-2.0f, v, 0.75f);
    p        = fmaf(1.5f, v2, p);
    float v4 = v2 * v2;
    p        = fmaf(-0.25f, v4, p);
    fo       = fmaf(25.0f * v2, p, (0.5f * v) * (3.0f - v2));

    float r = -37.5f * v;          // Horner for degree-5 f' (v^4 coeff = 0)
    r = fmaf(r, v, 150.0f);
    r = fmaf(r, v, -151.5f);
    r = fmaf(r, v, 37.5f);
    r = fmaf(r, v, 1.5f);
    dd = fabsf(r);

    float c1 = fminf(fmaxf(v, lo), mid);
    float c2 = fminf(fmaxf(v, mid), hi);
    Ao = fmaf(0.25f, c1 - lo, 0.5f * (c2 - mid));
}

__global__ __launch_bounds__(BLOCK, 1)
void vclin_kernel(const float* __restrict__ init,
                  const float* __restrict__ u_a,
                  const float* __restrict__ dtp,
                  const float* __restrict__ dxp,
                  int steps,
                  float* __restrict__ out)
{
    const int  b      = blockIdx.x;
    const int  t      = threadIdx.x;
    const int  j0     = t * CPT;
    const bool active = (j0 < NPTS);                 // threads 0..499
    const bool lastT  = active && (j0 + CPT >= NPTS); // thread 499

    __shared__ float s_lo, s_mid, s_hi;
    __shared__ float s_uf[BLOCK + 1];  // each thread's first point (next step's left value)
    __shared__ float s_gl[BLOCK];      // each thread's last edge flux

    if (t == 0) {
        // Derive the two-ramp A(u) parameters from this row's actual u_a grid.
        const float* ua = u_a + (size_t)b * NAP1;
        int jc = -1;
        for (int j = 0; j < NAP1; ++j) {
            if (ua[j] >= 0.5f) { jc = j; break; }
        }
        float lo, mid;
        if (jc < 0)       { lo = ua[NAP1 - 1]; mid = lo; }   // never crosses: A == 0
        else if (jc == 0) { lo = ua[0];        mid = lo; }   // crosses at/below start: single 0.5 ramp
        else              { lo = ua[jc - 1];   mid = ua[jc]; }
        s_lo = lo; s_mid = mid; s_hi = ua[NAP1 - 1];
    }
    const float dt     = dtp[0];
    const float dx     = dxp[0];
    const float lam    = dt / dx;
    const float inv_dx = 1.0f / dx;
    __syncthreads();
    const float lo = s_lo, mid = s_mid, hi = s_hi;

    // Register-resident state: 8 contiguous points per thread.
    float u[CPT];
#pragma unroll
    for (int c = 0; c < CPT; ++c) u[c] = 0.0f;

    if (active) {
        const float4* iv = (const float4*)(init + (size_t)b * NPTS + j0);
        float4 a0 = iv[0], a1 = iv[1];
        u[0] = a0.x; u[1] = a0.y; u[2] = a0.z; u[3] = a0.w;
        u[4] = a1.x; u[5] = a1.y; u[6] = a1.z; u[7] = a1.w;
        // trajectory step 0 = init
        float4* ov = (float4*)(out + (size_t)b * NPTS + j0);
        ov[0] = a0; ov[1] = a1;
    }

    for (int s = 1; s <= steps; ++s) {
        // Publish left-boundary value for the right neighbor's last edge.
        s_uf[t] = u[0];
        __syncthreads();
        const float unext = s_uf[t + 1];   // index BLOCK only read by inactive tail — harmless

        // Edge fluxes G[c] for edges j0+c (between points j0+c and j0+c+1),
        // rolling the point-local (f, |f'|, A) trio so each point is evaluated once.
        float G[CPT];
        float fp, dp, Ap;
        eval3(u[0], lo, mid, hi, fp, dp, Ap);
#pragma unroll
        for (int c = 0; c < CPT; ++c) {
            const float un = (c < CPT - 1) ? u[c + 1] : unext;
            float fn, dn, An;
            eval3(un, lo, mid, hi, fn, dn, An);
            const float M  = fmaxf(dp, dn);
            const float fh = fmaf(-0.5f * M, un - u[c], 0.5f * (fp + fn));
            const float Ah = (An - Ap) * inv_dx;
            G[c] = fh - Ah;
            fp = fn; dp = dn; Ap = An;
        }
        s_gl[t] = G[CPT - 1];
        __syncthreads();
        const float gleft = (t > 0) ? s_gl[t - 1] : 0.0f;

        if (active) {
            float nu[CPT];
            nu[0] = fmaf(-lam, G[0] - gleft, u[0]);
#pragma unroll
            for (int c = 1; c < CPT; ++c)
                nu[c] = fmaf(-lam, G[c] - G[c - 1], u[c]);
            if (t == 0)  nu[0]       = nu[1];        // u_new[0]   = u_new[1]
            if (lastT)   nu[CPT - 1] = nu[CPT - 2];  // u_new[N-1] = u_new[N-2]
#pragma unroll
            for (int c = 0; c < CPT; ++c) u[c] = nu[c];

            float4 a0 = make_float4(u[0], u[1], u[2], u[3]);
            float4 a1 = make_float4(u[4], u[5], u[6], u[7]);
            float4* ov = (float4*)(out + (size_t)s * (BATCHB * NPTS)
                                       + (size_t)b * NPTS + j0);
            ov[0] = a0; ov[1] = a1;
        }
        // No third barrier needed: next iteration's s_uf write happens after this
        // iteration's second barrier; all s_uf reads completed before it.
    }
}

extern "C" void kernel_launch(void* const* d_in, const int* in_sizes, int n_in,
                              void* d_out, int out_size)
{
    const float* init = (const float*)d_in[0];
    const float* u_a  = (const float*)d_in[1];
    const float* dtp  = (const float*)d_in[2];
    const float* dxp  = (const float*)d_in[3];
    (void)in_sizes; (void)n_in;

    // steps derived from the output trajectory length: out = (steps+1, B, N)
    const int steps = out_size / (BATCHB * NPTS) - 1;

    vclin_kernel<<<BATCHB, BLOCK>>>(init, u_a, dtp, dxp, steps, (float*)d_out);
}

// round 4
// speedup vs baseline: 1.2209x; 1.2209x over previous
#include <cuda_runtime.h>

#define BATCHB 128
#define NPTS   4000
#define NAP1   401
#define BLOCK  1024
#define CPT    4     // points per thread; 1000 active threads cover 4000 points

// f(u)  = 0.5*u*(3-u^2) + 25*u^2*(0.75 - 2u + 1.5u^2 - 0.25u^4)
// f'(u) = 1.5 + 37.5u - 151.5u^2 + 150u^3 - 37.5u^5
// A'(u) = inv_dx-scaled two-ramp closed form of the cumtrapz interpolation
//         (global constant offset dropped — it cancels in all differences):
//         qa*clamp(u,lo,mid) + qb*clamp(u,mid,hi),  qa=0.25/dx, qb=0.5/dx
__device__ __forceinline__ void eval3(float v, float lo, float mid, float hi,
                                      float qa, float qb,
                                      float& fo, float& dd, float& Ao)
{
    float v2 = v * v;
    float p  = fmaf(-2.0f, v, 0.75f);
    p        = fmaf(1.5f, v2, p);
    float v4 = v2 * v2;
    p        = fmaf(-0.25f, v4, p);
    fo       = fmaf(25.0f * v2, p, (0.5f * v) * (3.0f - v2));

    float r = -37.5f * v;          // Horner for degree-5 f' (v^4 coeff = 0)
    r = fmaf(r, v, 150.0f);
    r = fmaf(r, v, -151.5f);
    r = fmaf(r, v, 37.5f);
    r = fmaf(r, v, 1.5f);
    dd = fabsf(r);

    float c1 = fminf(fmaxf(v, lo), mid);
    float c2 = fminf(fmaxf(v, mid), hi);
    Ao = fmaf(qa, c1, qb * c2);
}

// Combined edge flux G = f_half - A_half (A already scaled by 1/dx).
__device__ __forceinline__ float edge_flux(float up, float fp, float dp, float Ap,
                                           float un, float fn, float dn, float An)
{
    float M = fmaxf(dp, dn);
    return fmaf(-0.5f * M, un - up, 0.5f * (fp + fn)) - (An - Ap);
}

// Dynamic SMEM layout: two double-buffered float4 halo arrays of (BLOCK+2).
//   s0[p][i] : trio+u of a thread's FIRST point   (read by left neighbor's right edge)
//   s7[p][i] : trio+u of a thread's LAST point    (read by right neighbor's left edge)
// Index offset +1 so sentinel entries [0] and [BLOCK+1] exist for the boundary threads.
#define HALO (BLOCK + 2)

__global__ __launch_bounds__(BLOCK, 1)
void vclin_kernel(const float* __restrict__ init,
                  const float* __restrict__ u_a,
                  const float* __restrict__ dtp,
                  const float* __restrict__ dxp,
                  int steps,
                  float* __restrict__ out)
{
    extern __shared__ float4 smem[];
    float4* s0 = smem;            // 2 * HALO entries
    float4* s7 = smem + 2 * HALO; // 2 * HALO entries

    const int  b      = blockIdx.x;
    const int  t      = threadIdx.x;
    const int  j0     = t * CPT;
    const bool active = (j0 < NPTS);                  // threads 0..999
    const bool lastT  = active && (j0 + CPT >= NPTS); // thread 999

    __shared__ float s_lo, s_mid, s_hi;

    if (t == 0) {
        // Derive the two-ramp A(u) parameters from this row's actual u_a grid.
        const float* ua = u_a + (size_t)b * NAP1;
        int jc = -1;
        for (int j = 0; j < NAP1; ++j) {
            if (ua[j] >= 0.5f) { jc = j; break; }
        }
        float lo, mid;
        if (jc < 0)       { lo = ua[NAP1 - 1]; mid = lo; }
        else if (jc == 0) { lo = ua[0];        mid = lo; }
        else              { lo = ua[jc - 1];   mid = ua[jc]; }
        s_lo = lo; s_mid = mid; s_hi = ua[NAP1 - 1];
        // Sentinels (values irrelevant: boundary updates are overridden, but keep finite)
        float4 z = make_float4(0.f, 0.f, 0.f, 0.f);
        s7[0] = z;            s7[HALO] = z;              // left sentinel, both parities
        s0[BLOCK + 1] = z;    s0[HALO + BLOCK + 1] = z;  // right sentinel, both parities
    }
    const float dt     = dtp[0];
    const float dx     = dxp[0];
    const float lam    = dt / dx;
    const float inv_dx = 1.0f / dx;
    const float qa     = 0.25f * inv_dx;
    const float qb     = 0.5f  * inv_dx;
    __syncthreads();
    const float lo = s_lo, mid = s_mid, hi = s_hi;

    float u0 = 0.f, u1 = 0.f, u2 = 0.f, u3 = 0.f;
    if (active) {
        float4 a = *(const float4*)(init + (size_t)b * NPTS + j0);
        u0 = a.x; u1 = a.y; u2 = a.z; u3 = a.w;
        *(float4*)(out + (size_t)b * NPTS + j0) = a;   // trajectory step 0 = init
    }

    for (int s = 1; s <= steps; ++s) {
        const int p = (s & 1) * HALO;   // parity offset into double buffers

        // Evaluate own 4 points once.
        float f0, d0, A0, f1, d1, A1, f2, d2, A2, f3, d3, A3;
        eval3(u0, lo, mid, hi, qa, qb, f0, d0, A0);
        eval3(u1, lo, mid, hi, qa, qb, f1, d1, A1);
        eval3(u2, lo, mid, hi, qa, qb, f2, d2, A2);
        eval3(u3, lo, mid, hi, qa, qb, f3, d3, A3);

        // Publish boundary trios; single barrier (double buffering makes it race-free:
        // writes to parity p at step s+2 are fenced behind barrier s+1, which postdates
        // every step-s read of parity p).
        s0[p + t + 1] = make_float4(u0, f0, d0, A0);
        s7[p + t + 1] = make_float4(u3, f3, d3, A3);
        __syncthreads();
        const float4 L = s7[p + t];      // left neighbor's last point (j0-1)
        const float4 R = s0[p + t + 2];  // right neighbor's first point (j0+4)

        // 5 edge fluxes: left halo edge + 4 own edges.
        float gL = edge_flux(L.x, L.y, L.z, L.w, u0, f0, d0, A0);
        float G0 = edge_flux(u0, f0, d0, A0,     u1, f1, d1, A1);
        float G1 = edge_flux(u1, f1, d1, A1,     u2, f2, d2, A2);
        float G2 = edge_flux(u2, f2, d2, A2,     u3, f3, d3, A3);
        float G3 = edge_flux(u3, f3, d3, A3,     R.x, R.y, R.z, R.w);

        float n0 = fmaf(-lam, G0 - gL, u0);
        float n1 = fmaf(-lam, G1 - G0, u1);
        float n2 = fmaf(-lam, G2 - G1, u2);
        float n3 = fmaf(-lam, G3 - G2, u3);
        if (t == 0) n0 = n1;        // u_new[0]   = u_new[1]
        if (lastT)  n3 = n2;        // u_new[N-1] = u_new[N-2]
        u0 = n0; u1 = n1; u2 = n2; u3 = n3;

        if (active) {
            *(float4*)(out + (size_t)s * (BATCHB * NPTS) + (size_t)b * NPTS + j0)
                = make_float4(u0, u1, u2, u3);
        }
    }
}

extern "C" void kernel_launch(void* const* d_in, const int* in_sizes, int n_in,
                              void* d_out, int out_size)
{
    const float* init = (const float*)d_in[0];
    const float* u_a  = (const float*)d_in[1];
    const float* dtp  = (const float*)d_in[2];
    const float* dxp  = (const float*)d_in[3];
    (void)in_sizes; (void)n_in;

    const int steps = out_size / (BATCHB * NPTS) - 1;

    const int smem_bytes = 4 * HALO * (int)sizeof(float4);  // 2 arrays x 2 buffers
    cudaFuncSetAttribute(vclin_kernel,
                         cudaFuncAttributeMaxDynamicSharedMemorySize, smem_bytes);

    vclin_kernel<<<BATCHB, BLOCK, smem_bytes>>>(init, u_a, dtp, dxp, steps,
                                                (float*)d_out);
}

// round 5
// speedup vs baseline: 1.4240x; 1.1664x over previous
#include <cuda_runtime.h>

#define BATCHB 128
#define NPTS   4000
#define NAP1   401
#define BLOCK  1024
#define CPT    4     // points per thread; 1000 active threads cover 4000 points
#define HALO   (BLOCK + 2)

typedef unsigned long long u64x;

// ---- packed fp32x2 helpers (Blackwell f32x2 pipe: one issue slot per pair) ----
__device__ __forceinline__ u64x pk2(float a, float b) {
    u64x r; asm("mov.b64 %0, {%1, %2};" : "=l"(r) : "f"(a), "f"(b)); return r;
}
__device__ __forceinline__ void up2(u64x p, float& a, float& b) {
    asm("mov.b64 {%0, %1}, %2;" : "=f"(a), "=f"(b) : "l"(p));
}
__device__ __forceinline__ u64x fma2_(u64x a, u64x b, u64x c) {
    u64x r; asm("fma.rn.f32x2 %0, %1, %2, %3;" : "=l"(r) : "l"(a), "l"(b), "l"(c)); return r;
}
__device__ __forceinline__ u64x mul2_(u64x a, u64x b) {
    u64x r; asm("mul.rn.f32x2 %0, %1, %2;" : "=l"(r) : "l"(a), "l"(b)); return r;
}
// broadcast one float into both halves (compile-time foldable)
__device__ __forceinline__ u64x bc2(float a) {
    unsigned int i = __float_as_uint(a);
    return ((u64x)i << 32) | i;
}

// Per-point quantities (both flux halves pre-combined):
//   f2 = 0.5*f(u)   = 0.75u + 9.375u^2 - 25.25u^3 + 18.75u^4 - 3.125u^6
//   d  = |0.5*f'(u)|, 0.5f' = 0.75 + 18.75u - 75.75u^2 + 75u^3 - 18.75u^5
//   A  = (1/dx)-scaled two-ramp closed form of the cumtrapz interp (offset dropped)
//   P  = f2 + A,  Q = f2 - A
// Edge flux: G(p,n) = P_p + Q_n + max(d_p,d_n)*(u_p - u_n)
__device__ __forceinline__ void eval_pair(
    float va, float vb,
    float lo, float mid, float hi, float qa, float qb,
    float& Pa, float& Qa, float& da,
    float& Pb, float& Qb, float& db)
{
    u64x v  = pk2(va, vb);
    u64x v2 = mul2_(v, v);

    // d = |0.5 f'|   (Horner, zero u^4 coeff absorbed via v2 head)
    u64x t = fma2_(v2, bc2(-18.75f), bc2(75.0f));
    t = fma2_(t, v, bc2(-75.75f));
    t = fma2_(t, v, bc2(18.75f));
    t = fma2_(t, v, bc2(0.75f));
    t &= 0x7FFFFFFF7FFFFFFFULL;          // packed fabs
    up2(t, da, db);

    // f2 = 0.5 f     (Horner, zero u^5 coeff absorbed via v2 head)
    u64x s = fma2_(v2, bc2(-3.125f), bc2(18.75f));
    s = fma2_(s, v, bc2(-25.25f));
    s = fma2_(s, v, bc2(9.375f));
    s = fma2_(s, v, bc2(0.75f));
    s = mul2_(s, v);
    float fa, fb; up2(s, fa, fb);

    // A (scalar clamps -> alu pipe, overlaps with packed fma chain)
    float c1a = fminf(fmaxf(va, lo), mid), c2a = fminf(fmaxf(va, mid), hi);
    float c1b = fminf(fmaxf(vb, lo), mid), c2b = fminf(fmaxf(vb, mid), hi);
    float Aa = fmaf(qa, c1a, qb * c2a);
    float Ab = fmaf(qa, c1b, qb * c2b);

    Pa = fa + Aa; Qa = fa - Aa;
    Pb = fb + Ab; Qb = fb - Ab;
}

__global__ __launch_bounds__(BLOCK, 1)
void vclin_kernel(const float* __restrict__ init,
                  const float* __restrict__ u_a,
                  const float* __restrict__ dtp,
                  const float* __restrict__ dxp,
                  int steps,
                  float* __restrict__ out)
{
    extern __shared__ float4 smem[];
    float4* s0 = smem;            // first-point halo, double-buffered: (u, Q, d, -)
    float4* s7 = smem + 2 * HALO; // last-point  halo, double-buffered: (u, P, d, -)

    const int  b      = blockIdx.x;
    const int  t      = threadIdx.x;
    const int  j0     = t * CPT;
    const bool active = (j0 < NPTS);
    const bool lastT  = active && (j0 + CPT >= NPTS);

    __shared__ float s_lo, s_mid, s_hi;

    if (t == 0) {
        const float* ua = u_a + (size_t)b * NAP1;
        int jc = -1;
        for (int j = 0; j < NAP1; ++j)
            if (ua[j] >= 0.5f) { jc = j; break; }
        float lo, mid;
        if (jc < 0)       { lo = ua[NAP1 - 1]; mid = lo; }
        else if (jc == 0) { lo = ua[0];        mid = lo; }
        else              { lo = ua[jc - 1];   mid = ua[jc]; }
        s_lo = lo; s_mid = mid; s_hi = ua[NAP1 - 1];
        float4 z = make_float4(0.f, 0.f, 0.f, 0.f);
        s7[0] = z;            s7[HALO] = z;               // left sentinels
        s0[BLOCK + 1] = z;    s0[HALO + BLOCK + 1] = z;   // right sentinels
    }
    const float dt     = dtp[0];
    const float dx     = dxp[0];
    const float nlam   = -dt / dx;
    const float inv_dx = 1.0f / dx;
    const float qa     = 0.25f * inv_dx;
    const float qb     = 0.5f  * inv_dx;
    __syncthreads();
    const float lo = s_lo, mid = s_mid, hi = s_hi;

    float u0 = 0.f, u1 = 0.f, u2 = 0.f, u3 = 0.f;
    float* op = out + (size_t)b * NPTS + j0;
    if (active) {
        float4 a = *(const float4*)(init + (size_t)b * NPTS + j0);
        u0 = a.x; u1 = a.y; u2 = a.z; u3 = a.w;
        *(float4*)op = a;                     // trajectory step 0 = init
    }

    for (int s = 1; s <= steps; ++s) {
        const int p = (s & 1) * HALO;

        float P0,Q0,d0, P1,Q1,d1, P2,Q2,d2, P3,Q3,d3;
        eval_pair(u0, u1, lo, mid, hi, qa, qb, P0,Q0,d0, P1,Q1,d1);
        eval_pair(u2, u3, lo, mid, hi, qa, qb, P2,Q2,d2, P3,Q3,d3);

        // Publish halos; single barrier (double buffering is parity-safe).
        s0[p + t + 1] = make_float4(u0, Q0, d0, 0.f);
        s7[p + t + 1] = make_float4(u3, P3, d3, 0.f);
        __syncthreads();
        const float4 L = s7[p + t];      // (uL, PL, dL)
        const float4 R = s0[p + t + 2];  // (uR, QR, dR)

        const float gL = fmaf(fmaxf(L.z, d0), L.x - u0, L.y + Q0);
        const float G0 = fmaf(fmaxf(d0, d1),  u0 - u1,  P0 + Q1);
        const float G1 = fmaf(fmaxf(d1, d2),  u1 - u2,  P1 + Q2);
        const float G2 = fmaf(fmaxf(d2, d3),  u2 - u3,  P2 + Q3);
        const float G3 = fmaf(fmaxf(d3, R.z), u3 - R.x, P3 + R.y);

        float n0 = fmaf(nlam, G0 - gL, u0);
        float n1 = fmaf(nlam, G1 - G0, u1);
        float n2 = fmaf(nlam, G2 - G1, u2);
        float n3 = fmaf(nlam, G3 - G2, u3);
        if (t == 0) n0 = n1;        // u_new[0]   = u_new[1]
        if (lastT)  n3 = n2;        // u_new[N-1] = u_new[N-2]
        u0 = n0; u1 = n1; u2 = n2; u3 = n3;

        op += (size_t)BATCHB * NPTS;
        if (active)
            *(float4*)op = make_float4(u0, u1, u2, u3);
    }
}

extern "C" void kernel_launch(void* const* d_in, const int* in_sizes, int n_in,
                              void* d_out, int out_size)
{
    const float* init = (const float*)d_in[0];
    const float* u_a  = (const float*)d_in[1];
    const float* dtp  = (const float*)d_in[2];
    const float* dxp  = (const float*)d_in[3];
    (void)in_sizes; (void)n_in;

    const int steps = out_size / (BATCHB * NPTS) - 1;

    const int smem_bytes = 4 * HALO * (int)sizeof(float4);
    cudaFuncSetAttribute(vclin_kernel,
                         cudaFuncAttributeMaxDynamicSharedMemorySize, smem_bytes);

    vclin_kernel<<<BATCHB, BLOCK, smem_bytes>>>(init, u_a, dtp, dxp, steps,
                                                (float*)d_out);
}